// round 11
// baseline (speedup 1.0000x reference)
#include <cuda_runtime.h>

#define TPB    256
#define IPT    4            // consecutive sorted i's per thread
#define WIN    1024         // i-window sort granularity (== TPB*IPT)
#define JCH    256          // j-chunk width
#define MAXN   16384
#define NWARP  (TPB / 32)

// Device-global state. Statically zero for the first (correctness) call; the
// finalizing block resets the accumulators each launch, so every graph replay
// sees identical initial state. g_is/g_jc are fully overwritten each launch.
__device__ unsigned long long g_C = 0ull, g_T = 0ull;
__device__ unsigned int g_M = 0u, g_done = 0u;
__device__ float2 g_is[MAXN];   // i windows, each 1024-run sorted by y asc
__device__ float2 g_jc[MAXN];   // j chunks: status==1 compacted, sorted by y asc, +inf padded

__device__ __forceinline__ float pos_inf() { return __int_as_float(0x7f800000); }
__device__ __forceinline__ float neg_inf() { return __int_as_float(0xff800000); }

// 2-op accumulate: c += (yh >= b)
__device__ __forceinline__ void acc_ge(unsigned int& c, float yhv, float b) {
    asm volatile("{\n\t.reg .pred p;\n\t"
                 "setp.ge.f32 p, %1, %2;\n\t"
                 "@p add.u32 %0, %0, 1;\n\t}"
                 : "+r"(c) : "f"(yhv), "f"(b));
}
// 3-op guarded accumulate: c += (jj < len) && (yh >= b)
__device__ __forceinline__ void acc_ge_lt(unsigned int& c, int jj, int len,
                                          float yhv, float b) {
    asm volatile("{\n\t.reg .pred p, q;\n\t"
                 "setp.lt.s32 p, %1, %2;\n\t"
                 "setp.ge.and.f32 q, %3, %4, p;\n\t"
                 "@q add.u32 %0, %0, 1;\n\t}"
                 : "+r"(c) : "r"(jj), "r"(len), "f"(yhv), "f"(b));
}

// ---------------------------------------------------------------------------
// Prep kernel: blocks [0, iwins) sort 1024-wide i-windows by y ascending.
// Blocks [iwins, iwins+jchunks) compact each 256-wide j-chunk (status==1),
// sort by y ascending, pad to 256 with +inf, and count M.
// ---------------------------------------------------------------------------
__global__ void __launch_bounds__(TPB)
prep_kernel(const float* __restrict__ y, const float* __restrict__ yh,
            const int* __restrict__ status, int n, int iwins) {
    __shared__ float2 sh[WIN];
    __shared__ unsigned int swcnt[NWARP];
    const int tid = threadIdx.x;
    const int b = (int)blockIdx.x;

    if (b < iwins) {
        // ---- i-window sort: 1024 elems, keys y, payload yh ----
        const int base = b * WIN;
        for (int e = tid; e < WIN; e += TPB) {
            int i = base + e;
            bool v = (i < n);
            sh[e] = make_float2(v ? y[i] : neg_inf(), v ? yh[i] : neg_inf());
        }
        for (int k = 2; k <= WIN; k <<= 1) {
            for (int s = k >> 1; s > 0; s >>= 1) {
                __syncthreads();
                for (int t = tid; t < WIN / 2; t += TPB) {
                    int i = ((t & ~(s - 1)) << 1) | (t & (s - 1));
                    int j = i + s;
                    bool up = ((i & k) == 0);
                    float2 a = sh[i], c2 = sh[j];
                    if ((a.x > c2.x) == up) { sh[i] = c2; sh[j] = a; }
                }
            }
        }
        __syncthreads();
        for (int e = tid; e < WIN; e += TPB)
            g_is[base + e] = sh[e];
    } else {
        // ---- j-chunk compact + sort ----
        const int c = b - iwins;
        const int j = c * JCH + tid;
        const bool jv = (j < n);
        float yj  = jv ? y[j]  : 0.0f;
        float yhj = jv ? yh[j] : 0.0f;
        const bool keep = jv && (status[j] == 1);

        const int wid = tid >> 5, lid = tid & 31;
        unsigned int bal = __ballot_sync(0xffffffffu, keep);
        unsigned int pre = __popc(bal & ((1u << lid) - 1u));
        if (lid == 0) swcnt[wid] = __popc(bal);

        sh[tid] = make_float2(pos_inf(), pos_inf());   // padding sorts last
        __syncthreads();

        unsigned int base2 = 0, m = 0;
#pragma unroll
        for (int w = 0; w < NWARP; w++) {
            if (w < wid) base2 += swcnt[w];
            m += swcnt[w];
        }
        if (keep) sh[base2 + pre] = make_float2(yj, yhj);
        __syncthreads();
        if (tid == 0 && m) atomicAdd(&g_M, m);

        for (int k = 2; k <= JCH; k <<= 1) {
            for (int s = k >> 1; s > 0; s >>= 1) {
                __syncthreads();
                if (tid < JCH / 2) {
                    int i = ((tid & ~(s - 1)) << 1) | (tid & (s - 1));
                    int jx = i + s;
                    bool up = ((i & k) == 0);
                    float2 a = sh[i], d = sh[jx];
                    if ((a.x > d.x) == up) { sh[i] = d; sh[jx] = a; }
                }
            }
        }
        __syncthreads();
        g_jc[c * JCH + tid] = sh[tid];
    }
}

// ---------------------------------------------------------------------------
// Pair kernel. For each (i-window, j-chunk):
//   len_k = #{j : yc_j <= y_ik} via branchless binary search (T += len_k)
//   C: scan prefix [0, len) with only the yh condition (2 ops/pair)
// ---------------------------------------------------------------------------
__global__ void __launch_bounds__(TPB, 6)
pair_kernel(float* __restrict__ out, int nblocks) {
    __shared__ float syc[JCH];
    __shared__ float syh[JCH];
    __shared__ unsigned long long sred[NWARP];

    const int tid = threadIdx.x;
    const int wid = tid >> 5, lid = tid & 31;

    float2 v = g_jc[(int)blockIdx.y * JCH + tid];
    syc[tid] = v.x;
    syh[tid] = v.y;
    __syncthreads();

    // 4 consecutive sorted ranks per lane; warp spans 128 consecutive ranks
    const int ibase = (int)blockIdx.x * WIN + wid * (32 * IPT) + lid * IPT;
    float yi[IPT], yhi[IPT];
#pragma unroll
    for (int k = 0; k < IPT; k++) {
        float2 a = g_is[ibase + k];
        yi[k] = a.x; yhi[k] = a.y;
    }

    // branchless prefix lengths (exact count of yc_j <= y_i; +inf pad safe)
    int len[IPT];
    unsigned int tcnt = 0u;
#pragma unroll
    for (int k = 0; k < IPT; k++) {
        int l = 0;
#pragma unroll
        for (int s = 128; s; s >>= 1)
            if (syc[l + s - 1] <= yi[k]) l += s;
        len[k] = l;
        tcnt += (unsigned int)l;
    }
    int lmin = min(min(len[0], len[1]), min(len[2], len[3]));
    int lmax = max(max(len[0], len[1]), max(len[2], len[3]));

    unsigned int ccnt = 0u;
    int jj = 0;
#pragma unroll 4
    for (; jj < lmin; jj++) {          // bulk: 2 ops/pair, yc implied by prefix
        float b = syh[jj];             // uniform jj -> broadcast LDS
#pragma unroll
        for (int k = 0; k < IPT; k++) acc_ge(ccnt, yhi[k], b);
    }
    for (; jj < lmax; jj++) {          // tail: ~1-2 iters (adjacent ranks)
        float b = syh[jj];
#pragma unroll
        for (int k = 0; k < IPT; k++) acc_ge_lt(ccnt, jj, len[k], yhi[k], b);
    }

    // warp reduce, pack (t<<32 | c); per-warp sums fit 32 bits comfortably
#pragma unroll
    for (int off = 16; off; off >>= 1) {
        tcnt += __shfl_down_sync(0xffffffffu, tcnt, off);
        ccnt += __shfl_down_sync(0xffffffffu, ccnt, off);
    }
    if (lid == 0)
        sred[wid] = ((unsigned long long)tcnt << 32) | (unsigned long long)ccnt;
    __syncthreads();

    if (tid == 0) {
        unsigned long long s = 0ull;
#pragma unroll
        for (int w = 0; w < NWARP; w++) s += sred[w];
        atomicAdd(&g_T, s >> 32);
        atomicAdd(&g_C, s & 0xffffffffull);
        __threadfence();
        unsigned int old = atomicAdd(&g_done, 1u);
        if (old == (unsigned int)(nblocks - 1)) {
            __threadfence();
            double M = (double)atomicAdd(&g_M, 0u);
            double c = (double)atomicAdd(&g_C, 0ull) - M;  // drop diagonal
            double t = (double)atomicAdd(&g_T, 0ull) - M;
            out[0] = (float)(c / t);
            // reset for next graph replay
            g_C = 0ull; g_T = 0ull; g_M = 0u; g_done = 0u;
        }
    }
}

extern "C" void kernel_launch(void* const* d_in, const int* in_sizes, int n_in,
                              void* d_out, int out_size) {
    const float* y      = (const float*)d_in[0];
    const float* yh     = (const float*)d_in[1];
    const int*   status = (const int*)d_in[2];
    int n = in_sizes[0];

    int iwins   = (n + WIN - 1) / WIN;    // 16
    int jchunks = (n + JCH - 1) / JCH;    // 64

    prep_kernel<<<iwins + jchunks, TPB>>>(y, yh, status, n, iwins);

    dim3 grid(iwins, jchunks);
    pair_kernel<<<grid, TPB>>>((float*)d_out, iwins * jchunks);
}